// round 7
// baseline (speedup 1.0000x reference)
#include <cuda_runtime.h>
#include <math.h>

#define TT    256
#define IN_F  1024
#define HID_F 1024
#define OUT_F 1024
#define BB    128
#define HB    (HID_F * BB)

// Scratch (allocation-free rule: __device__ globals)
// g_S[t] = pre-activation state: Wxh@x_t + bh + Whh@h_{t-1}; h_t = tanh(g_S[t])
__device__ float g_S[(size_t)TT * HB];      // 134 MB

// ---------------------------------------------------------------------------
// Packed f32x2 helpers (B300: 3-reg FFMA is half-rate; FFMA2 restores 2x)
// ---------------------------------------------------------------------------
__device__ __forceinline__ unsigned long long dup2(float x)
{
    unsigned long long r;
    asm("mov.b64 %0, {%1, %1};" : "=l"(r) : "f"(x));
    return r;
}
__device__ __forceinline__ void unpack2(unsigned long long v, float& lo, float& hi)
{
    asm("mov.b64 {%0, %1}, %2;" : "=f"(lo), "=f"(hi) : "l"(v));
}
__device__ __forceinline__ void ffma2(unsigned long long& d,
                                      unsigned long long a, unsigned long long b)
{
    asm("fma.rn.f32x2 %0, %1, %2, %0;" : "+l"(d) : "l"(a), "l"(b));
}

// ---------------------------------------------------------------------------
// C[t] = W(1024 x K) @ f(X[t])(K x 128) + bias  (tile 128x128, BK=8, 8x8/thr)
// TANHX: apply tanhf to X elements on load (X holds pre-activation state).
// Inner loop: 32 FFMA2 per kk (acc pairs along n).
// ---------------------------------------------------------------------------
template <bool TANHX>
__global__ __launch_bounds__(256) void gemm_full(
    const float* __restrict__ W, const float* __restrict__ Xb,
    const float* __restrict__ bias, float* __restrict__ Cb,
    int K, long long xstride, long long cstride)
{
    __shared__ float Ws[8][128];   // transposed: Ws[k][m]
    __shared__ float Xs[8][128];

    const int tid = threadIdx.x;
    const int m0  = blockIdx.x * 128;
    const float* X = Xb + (long long)blockIdx.y * xstride;
    float*       C = Cb + (long long)blockIdx.y * cstride;

    const int tm = (tid >> 4) * 8;
    const int tn = (tid & 15) * 8;

    unsigned long long acc[8][4];   // 8 m-rows x 4 n-pairs
#pragma unroll
    for (int i = 0; i < 8; i++)
#pragma unroll
        for (int j = 0; j < 4; j++) acc[i][j] = 0ull;

    const int wrow = tid >> 1;
    const int wkq  = (tid & 1) * 4;
    const int xrow = tid >> 5;
    const int xcol = (tid & 31) * 4;

    for (int k0 = 0; k0 < K; k0 += 8) {
        float4 w = *(const float4*)(W + (long long)(m0 + wrow) * K + k0 + wkq);
        float4 x = *(const float4*)(X + (long long)(k0 + xrow) * BB + xcol);
        if (TANHX) {
            x.x = tanhf(x.x); x.y = tanhf(x.y);
            x.z = tanhf(x.z); x.w = tanhf(x.w);
        }
        __syncthreads();
        Ws[wkq + 0][wrow] = w.x;
        Ws[wkq + 1][wrow] = w.y;
        Ws[wkq + 2][wrow] = w.z;
        Ws[wkq + 3][wrow] = w.w;
        *(float4*)&Xs[xrow][xcol] = x;
        __syncthreads();
#pragma unroll
        for (int kk = 0; kk < 8; kk++) {
            float4 a0 = *(const float4*)&Ws[kk][tm];
            float4 a1 = *(const float4*)&Ws[kk][tm + 4];
            ulonglong2 b0 = *(const ulonglong2*)&Xs[kk][tn];
            ulonglong2 b1 = *(const ulonglong2*)&Xs[kk][tn + 4];
            unsigned long long ad[8];
            ad[0] = dup2(a0.x); ad[1] = dup2(a0.y);
            ad[2] = dup2(a0.z); ad[3] = dup2(a0.w);
            ad[4] = dup2(a1.x); ad[5] = dup2(a1.y);
            ad[6] = dup2(a1.z); ad[7] = dup2(a1.w);
#pragma unroll
            for (int i = 0; i < 8; i++) {
                ffma2(acc[i][0], ad[i], b0.x);
                ffma2(acc[i][1], ad[i], b0.y);
                ffma2(acc[i][2], ad[i], b1.x);
                ffma2(acc[i][3], ad[i], b1.y);
            }
        }
    }

#pragma unroll
    for (int i = 0; i < 8; i++) {
        const float bv = bias[m0 + tm + i];
        float o[8];
        unpack2(acc[i][0], o[0], o[1]);
        unpack2(acc[i][1], o[2], o[3]);
        unpack2(acc[i][2], o[4], o[5]);
        unpack2(acc[i][3], o[6], o[7]);
        float4 o0 = make_float4(o[0] + bv, o[1] + bv, o[2] + bv, o[3] + bv);
        float4 o1 = make_float4(o[4] + bv, o[5] + bv, o[6] + bv, o[7] + bv);
        float* crow = C + (long long)(m0 + tm + i) * BB + tn;
        *(float4*)(crow)     = o0;
        *(float4*)(crow + 4) = o1;
    }
}

// ---------------------------------------------------------------------------
// One recurrence step (launched per t):
//   dst += Whh[:, ks] @ tanh?(src[ks, :])     via atomicAdd (REDG)
// grid (16 m-tiles, 8 k-splits) = 128 CTAs, 256 threads.
// Double-buffered smem pipeline; 16 FFMA2 per kk.
// ---------------------------------------------------------------------------
__global__ __launch_bounds__(256) void rnn_step(
    const float* __restrict__ Whh, const float* __restrict__ src,
    float* __restrict__ dst, int do_tanh)
{
    __shared__ float Ws[2][8][64];    // [buf][k][m]  4 KB
    __shared__ float Xs[2][8][128];   // [buf][k][b]  8 KB

    const int tid   = threadIdx.x;
    const int m0    = blockIdx.x * 64;
    const int kbase = blockIdx.y * 128;

    const float* Wp = Whh + (long long)kbase;
    const float* Hs = src + (long long)kbase * BB;

    const int tm = (tid >> 4) * 4;    // 0..60
    const int tn = (tid & 15) * 8;    // 0..120

    const int wrow = tid >> 2;        // 0..63
    const int wkq  = (tid & 3) * 2;   // 0,2,4,6
    const int xrow = tid >> 5;        // 0..7
    const int xcol = (tid & 31) * 4;  // 0..124

    unsigned long long acc[4][4];     // 4 m-rows x 4 n-pairs
#pragma unroll
    for (int i = 0; i < 4; i++)
#pragma unroll
        for (int j = 0; j < 4; j++) acc[i][j] = 0ull;

    // prefetch chunk 0
    {
        float2 w = *(const float2*)(Wp + (long long)(m0 + wrow) * HID_F + wkq);
        float4 x = *(const float4*)(Hs + (long long)xrow * BB + xcol);
        if (do_tanh) {
            x.x = tanhf(x.x); x.y = tanhf(x.y);
            x.z = tanhf(x.z); x.w = tanhf(x.w);
        }
        Ws[0][wkq + 0][wrow] = w.x;
        Ws[0][wkq + 1][wrow] = w.y;
        *(float4*)&Xs[0][xrow][xcol] = x;
    }
    __syncthreads();

#pragma unroll 2
    for (int c = 0; c < 16; c++) {
        const int buf = c & 1;
        float2 wn; float4 xn;
        if (c < 15) {
            const int kk0 = (c + 1) * 8;
            wn = *(const float2*)(Wp + (long long)(m0 + wrow) * HID_F + kk0 + wkq);
            xn = *(const float4*)(Hs + (long long)(kk0 + xrow) * BB + xcol);
            if (do_tanh) {
                xn.x = tanhf(xn.x); xn.y = tanhf(xn.y);
                xn.z = tanhf(xn.z); xn.w = tanhf(xn.w);
            }
        }
#pragma unroll
        for (int kk = 0; kk < 8; kk++) {
            float4 av = *(const float4*)&Ws[buf][kk][tm];
            ulonglong2 b0 = *(const ulonglong2*)&Xs[buf][kk][tn];
            ulonglong2 b1 = *(const ulonglong2*)&Xs[buf][kk][tn + 4];
            unsigned long long ad[4];
            ad[0] = dup2(av.x); ad[1] = dup2(av.y);
            ad[2] = dup2(av.z); ad[3] = dup2(av.w);
#pragma unroll
            for (int i = 0; i < 4; i++) {
                ffma2(acc[i][0], ad[i], b0.x);
                ffma2(acc[i][1], ad[i], b0.y);
                ffma2(acc[i][2], ad[i], b1.x);
                ffma2(acc[i][3], ad[i], b1.y);
            }
        }
        if (c < 15) {
            Ws[buf ^ 1][wkq + 0][wrow] = wn.x;
            Ws[buf ^ 1][wkq + 1][wrow] = wn.y;
            *(float4*)&Xs[buf ^ 1][xrow][xcol] = xn;
        }
        __syncthreads();
    }

    // accumulate partials into dst (REDG; cross-launch visibility via kernel
    // boundary)
#pragma unroll
    for (int i = 0; i < 4; i++) {
        float o[8];
        unpack2(acc[i][0], o[0], o[1]);
        unpack2(acc[i][1], o[2], o[3]);
        unpack2(acc[i][2], o[4], o[5]);
        unpack2(acc[i][3], o[6], o[7]);
        float* pr = dst + (long long)(m0 + tm + i) * BB + tn;
#pragma unroll
        for (int j = 0; j < 8; j++)
            atomicAdd(pr + j, o[j]);
    }
}

// h_final = tanh(S[T-1])
__global__ __launch_bounds__(256) void copy_final(float* __restrict__ out)
{
    const int idx = blockIdx.x * 256 + threadIdx.x;   // 512 * 256 = HB
    out[(long long)TT * OUT_F * BB + idx] =
        tanhf(g_S[(long long)(TT - 1) * HB + idx]);
}

// ---------------------------------------------------------------------------
extern "C" void kernel_launch(void* const* d_in, const int* in_sizes, int n_in,
                              void* d_out, int out_size)
{
    (void)in_sizes; (void)n_in; (void)out_size;
    const float* inputs = (const float*)d_in[0];   // [T, IN, B]
    const float* h_prev = (const float*)d_in[1];   // [HID, B]
    const float* Wxh    = (const float*)d_in[2];   // [HID, IN]
    const float* Whh    = (const float*)d_in[3];   // [HID, HID]
    const float* Why    = (const float*)d_in[4];   // [OUT, HID]
    const float* bh     = (const float*)d_in[5];   // [HID]
    const float* by     = (const float*)d_in[6];   // [OUT]
    float* out = (float*)d_out;                    // ys [T,OUT,B] then h_final

    float* pS = nullptr;
    cudaGetSymbolAddress((void**)&pS, g_S);

    // 1) S[t] = Wxh @ x_t + bh, all t in parallel
    gemm_full<false><<<dim3(8, TT), 256>>>(Wxh, inputs, bh, pS,
                                           IN_F, (long long)IN_F * BB,
                                           (long long)HB);

    // 2) serial recurrence: S[t] += Whh @ tanh?(S[t-1]); one launch per step
    for (int t = 0; t < TT; ++t) {
        const float* src = (t == 0) ? h_prev : (pS + (long long)(t - 1) * HB);
        rnn_step<<<dim3(16, 8), 256>>>(Whh, src, pS + (long long)t * HB,
                                       t == 0 ? 0 : 1);
    }

    // 3) y_t = Why @ tanh(S[t]) + by, all t in parallel, into d_out
    gemm_full<true><<<dim3(8, TT), 256>>>(Why, pS, by, out,
                                          HID_F, (long long)HB,
                                          (long long)OUT_F * BB);

    // 4) h_final
    copy_final<<<512, 256>>>(out);
}

// round 9
// speedup vs baseline: 1.1125x; 1.1125x over previous
#include <cuda_runtime.h>
#include <cuda_bf16.h>
#include <mma.h>
#include <math.h>
#include <stdint.h>

using namespace nvcuda;

#define TT    256
#define IN_F  1024
#define HID_F 1024
#define OUT_F 1024
#define BB    128
#define HB    (HID_F * BB)
#define KDIM  1024
#define CH    32          // K chunk per mainloop iteration
#define KPA   40          // A smem k-pitch (conflict-free, 32B-aligned frags)
#define KPB   136         // B smem b-pitch (conflict-free, 32B-aligned frags)

// Scratch (__device__ globals; no allocations allowed)
__device__ float g_S[(size_t)TT * HB];             // pre-activation state (134 MB)
__device__ __nv_bfloat16 g_W1hi[(size_t)HID_F * IN_F];
__device__ __nv_bfloat16 g_W1lo[(size_t)HID_F * IN_F];
__device__ __nv_bfloat16 g_W2hi[(size_t)OUT_F * HID_F];
__device__ __nv_bfloat16 g_W2lo[(size_t)OUT_F * HID_F];

// ---------------------------------------------------------------------------
// Elementwise weight split: hi = bf16(w), lo = bf16(w - hi)
// ---------------------------------------------------------------------------
__global__ __launch_bounds__(256) void split_w(
    const float* __restrict__ W, __nv_bfloat16* __restrict__ hi,
    __nv_bfloat16* __restrict__ lo, int n)
{
    int i = blockIdx.x * 256 + threadIdx.x;
    if (i < n) {
        float v = W[i];
        __nv_bfloat16 h = __float2bfloat16_rn(v);
        hi[i] = h;
        lo[i] = __float2bfloat16_rn(v - __bfloat162float(h));
    }
}

// ---------------------------------------------------------------------------
// Tensor-core GEMM (wmma bf16, 3-pass split): one (m-tile, t) per CTA.
//   C[t][m0:m0+128][0:128] = Whi@Xhi + Whi@Xlo + Wlo@Xhi     (fp32 accum)
// W*: bf16 [M][K] (pre-split). X: fp32 [T][K][B] — split + (optional tanh)
// applied in-kernel while staging each K-chunk to smem.
// 256 threads = 8 warps, 4x2 warp grid, each warp 32(m) x 64(n), 2x4 frags.
// ---------------------------------------------------------------------------
template <bool TANH>
__global__ __launch_bounds__(256) void wmma_gemm(
    const __nv_bfloat16* __restrict__ Whi, const __nv_bfloat16* __restrict__ Wlo,
    const float* __restrict__ Xb, long long xstride,
    float* __restrict__ Cb, long long cstride)
{
    __shared__ __align__(32) __nv_bfloat16 Ah[128][KPA];
    __shared__ __align__(32) __nv_bfloat16 Al[128][KPA];
    __shared__ __align__(32) __nv_bfloat16 Bh[CH][KPB];
    __shared__ __align__(32) __nv_bfloat16 Bl[CH][KPB];

    const int tid = threadIdx.x;
    const int wid = tid >> 5;
    const int m0  = blockIdx.x * 128;
    const int t   = blockIdx.y;
    const int wm  = wid >> 1;        // 0..3  -> rows wm*32..+32
    const int wn  = wid & 1;         // 0..1  -> cols wn*64..+64

    const __nv_bfloat16* WhP = Whi + (size_t)m0 * KDIM;
    const __nv_bfloat16* WlP = Wlo + (size_t)m0 * KDIM;
    const float*         X   = Xb + (long long)t * xstride;

    // A staging map: 2 uint4 (8 bf16) per thread per array
    const int arow = tid >> 1;                 // v = tid + q*256 -> row = v>>1? no:
    // v in [0,512): row = v>>2 (0..127), kq = (v&3)*8
    // B staging map: 4 float4 per thread: u in [0,1024): krow = u>>5, bcol=(u&31)*4

    wmma::fragment<wmma::accumulator, 16, 16, 16, float> acc[2][4];
#pragma unroll
    for (int i = 0; i < 2; i++)
#pragma unroll
        for (int j = 0; j < 4; j++) wmma::fill_fragment(acc[i][j], 0.0f);

    uint4  aH[2], aL[2];
    float4 bx[4];

    auto load_regs = [&](int k0) {
#pragma unroll
        for (int q = 0; q < 2; q++) {
            const int v = tid + q * 256;
            const int row = v >> 2, kq = (v & 3) * 8;
            aH[q] = *(const uint4*)(WhP + (size_t)row * KDIM + k0 + kq);
            aL[q] = *(const uint4*)(WlP + (size_t)row * KDIM + k0 + kq);
        }
#pragma unroll
        for (int q = 0; q < 4; q++) {
            const int u = tid + q * 256;
            const int krow = u >> 5, bcol = (u & 31) * 4;
            bx[q] = *(const float4*)(X + (long long)(k0 + krow) * BB + bcol);
        }
    };

    load_regs(0);

    for (int c = 0; c < KDIM / CH; c++) {
        // stage regs -> smem (split B on the fly)
#pragma unroll
        for (int q = 0; q < 2; q++) {
            const int v = tid + q * 256;
            const int row = v >> 2, kq = (v & 3) * 8;
            *(uint4*)&Ah[row][kq] = aH[q];
            *(uint4*)&Al[row][kq] = aL[q];
        }
#pragma unroll
        for (int q = 0; q < 4; q++) {
            const int u = tid + q * 256;
            const int krow = u >> 5, bcol = (u & 31) * 4;
            float4 f = bx[q];
            if (TANH) {
                f.x = tanhf(f.x); f.y = tanhf(f.y);
                f.z = tanhf(f.z); f.w = tanhf(f.w);
            }
            __nv_bfloat16 h0 = __float2bfloat16_rn(f.x);
            __nv_bfloat16 h1 = __float2bfloat16_rn(f.y);
            __nv_bfloat16 h2 = __float2bfloat16_rn(f.z);
            __nv_bfloat16 h3 = __float2bfloat16_rn(f.w);
            __nv_bfloat16 l0 = __float2bfloat16_rn(f.x - __bfloat162float(h0));
            __nv_bfloat16 l1 = __float2bfloat16_rn(f.y - __bfloat162float(h1));
            __nv_bfloat16 l2 = __float2bfloat16_rn(f.z - __bfloat162float(h2));
            __nv_bfloat16 l3 = __float2bfloat16_rn(f.w - __bfloat162float(h3));
            *(__nv_bfloat162*)&Bh[krow][bcol]     = __nv_bfloat162(h0, h1);
            *(__nv_bfloat162*)&Bh[krow][bcol + 2] = __nv_bfloat162(h2, h3);
            *(__nv_bfloat162*)&Bl[krow][bcol]     = __nv_bfloat162(l0, l1);
            *(__nv_bfloat162*)&Bl[krow][bcol + 2] = __nv_bfloat162(l2, l3);
        }
        __syncthreads();

        if (c + 1 < KDIM / CH) load_regs((c + 1) * CH);

        // compute this chunk: 2 k16 sub-steps
#pragma unroll
        for (int kk = 0; kk < CH; kk += 16) {
            wmma::fragment<wmma::matrix_a, 16, 16, 16, __nv_bfloat16,
                           wmma::row_major> fah[2], fal[2];
            wmma::fragment<wmma::matrix_b, 16, 16, 16, __nv_bfloat16,
                           wmma::row_major> fbh[4], fbl[4];
#pragma unroll
            for (int i = 0; i < 2; i++) {
                wmma::load_matrix_sync(fah[i], &Ah[wm * 32 + i * 16][kk], KPA);
                wmma::load_matrix_sync(fal[i], &Al[wm * 32 + i * 16][kk], KPA);
            }
#pragma unroll
            for (int j = 0; j < 4; j++) {
                wmma::load_matrix_sync(fbh[j], &Bh[kk][wn * 64 + j * 16], KPB);
                wmma::load_matrix_sync(fbl[j], &Bl[kk][wn * 64 + j * 16], KPB);
            }
#pragma unroll
            for (int i = 0; i < 2; i++)
#pragma unroll
                for (int j = 0; j < 4; j++) {
                    wmma::mma_sync(acc[i][j], fah[i], fbh[j], acc[i][j]);
                    wmma::mma_sync(acc[i][j], fah[i], fbl[j], acc[i][j]);
                    wmma::mma_sync(acc[i][j], fal[i], fbh[j], acc[i][j]);
                }
        }
        __syncthreads();
    }

    // epilogue: direct store (bias added by bias_add kernel)
    float* C = Cb + (long long)t * cstride;
#pragma unroll
    for (int i = 0; i < 2; i++)
#pragma unroll
        for (int j = 0; j < 4; j++)
            wmma::store_matrix_sync(
                C + (long long)(m0 + wm * 32 + i * 16) * BB + wn * 64 + j * 16,
                acc[i][j], BB, wmma::mem_row_major);
}

// C[t][m][b] += bias[m]   over n elements (n = TT*1024*128)
__global__ __launch_bounds__(256) void bias_add(
    float* __restrict__ C, const float* __restrict__ bias)
{
    const long long idx = (long long)blockIdx.x * 256 + threadIdx.x;
    C[idx] += bias[(idx >> 7) & 1023];
}

// ---------------------------------------------------------------------------
// Recurrence step (proven R6 kernel): dst += Whh[:,ks] @ tanh?(src[ks,:])
// ---------------------------------------------------------------------------
__global__ __launch_bounds__(256) void rnn_step(
    const float* __restrict__ Whh, const float* __restrict__ src,
    float* __restrict__ dst, int do_tanh)
{
    __shared__ float Ws[2][8][64];
    __shared__ float Xs[2][8][128];

    const int tid   = threadIdx.x;
    const int m0    = blockIdx.x * 64;
    const int kbase = blockIdx.y * 128;

    const float* Wp = Whh + (long long)kbase;
    const float* Hs = src + (long long)kbase * BB;

    const int tm = (tid >> 4) * 4;
    const int tn = (tid & 15) * 8;
    const int wrow = tid >> 2;
    const int wkq  = (tid & 3) * 2;
    const int xrow = tid >> 5;
    const int xcol = (tid & 31) * 4;

    float acc[4][8];
#pragma unroll
    for (int i = 0; i < 4; i++)
#pragma unroll
        for (int j = 0; j < 8; j++) acc[i][j] = 0.f;

    {
        float2 w = *(const float2*)(Wp + (long long)(m0 + wrow) * HID_F + wkq);
        float4 x = *(const float4*)(Hs + (long long)xrow * BB + xcol);
        if (do_tanh) {
            x.x = tanhf(x.x); x.y = tanhf(x.y);
            x.z = tanhf(x.z); x.w = tanhf(x.w);
        }
        Ws[0][wkq + 0][wrow] = w.x;
        Ws[0][wkq + 1][wrow] = w.y;
        *(float4*)&Xs[0][xrow][xcol] = x;
    }
    __syncthreads();

#pragma unroll 2
    for (int c = 0; c < 16; c++) {
        const int buf = c & 1;
        float2 wn2; float4 xn;
        if (c < 15) {
            const int kk0 = (c + 1) * 8;
            wn2 = *(const float2*)(Wp + (long long)(m0 + wrow) * HID_F + kk0 + wkq);
            xn  = *(const float4*)(Hs + (long long)(kk0 + xrow) * BB + xcol);
            if (do_tanh) {
                xn.x = tanhf(xn.x); xn.y = tanhf(xn.y);
                xn.z = tanhf(xn.z); xn.w = tanhf(xn.w);
            }
        }
#pragma unroll
        for (int kk = 0; kk < 8; kk++) {
            float a[4], bb[8];
            *(float4*)&a[0]  = *(const float4*)&Ws[buf][kk][tm];
            *(float4*)&bb[0] = *(const float4*)&Xs[buf][kk][tn];
            *(float4*)&bb[4] = *(const float4*)&Xs[buf][kk][tn + 4];
#pragma unroll
            for (int i = 0; i < 4; i++)
#pragma unroll
                for (int j = 0; j < 8; j++)
                    acc[i][j] += a[i] * bb[j];
        }
        if (c < 15) {
            Ws[buf ^ 1][wkq + 0][wrow] = wn2.x;
            Ws[buf ^ 1][wkq + 1][wrow] = wn2.y;
            *(float4*)&Xs[buf ^ 1][xrow][xcol] = xn;
        }
        __syncthreads();
    }

#pragma unroll
    for (int i = 0; i < 4; i++) {
        float* pr = dst + (long long)(m0 + tm + i) * BB + tn;
#pragma unroll
        for (int j = 0; j < 8; j++)
            atomicAdd(pr + j, acc[i][j]);
    }
}

// h_final = tanh(S[T-1])
__global__ __launch_bounds__(256) void copy_final(float* __restrict__ out)
{
    const int idx = blockIdx.x * 256 + threadIdx.x;
    out[(long long)TT * OUT_F * BB + idx] =
        tanhf(g_S[(long long)(TT - 1) * HB + idx]);
}

// ---------------------------------------------------------------------------
extern "C" void kernel_launch(void* const* d_in, const int* in_sizes, int n_in,
                              void* d_out, int out_size)
{
    (void)in_sizes; (void)n_in; (void)out_size;
    const float* inputs = (const float*)d_in[0];
    const float* h_prev = (const float*)d_in[1];
    const float* Wxh    = (const float*)d_in[2];
    const float* Whh    = (const float*)d_in[3];
    const float* Why    = (const float*)d_in[4];
    const float* bh     = (const float*)d_in[5];
    const float* by     = (const float*)d_in[6];
    float* out = (float*)d_out;

    float* pS = nullptr;
    __nv_bfloat16 *pW1h, *pW1l, *pW2h, *pW2l;
    cudaGetSymbolAddress((void**)&pS,  g_S);
    cudaGetSymbolAddress((void**)&pW1h, g_W1hi);
    cudaGetSymbolAddress((void**)&pW1l, g_W1lo);
    cudaGetSymbolAddress((void**)&pW2h, g_W2hi);
    cudaGetSymbolAddress((void**)&pW2l, g_W2lo);

    // weight splits
    split_w<<<4096, 256>>>(Wxh, pW1h, pW1l, HID_F * IN_F);
    split_w<<<4096, 256>>>(Why, pW2h, pW2l, OUT_F * HID_F);

    // 1) S[t] = Wxh @ x_t + bh  (tensor cores)
    wmma_gemm<false><<<dim3(8, TT), 256>>>(pW1h, pW1l, inputs,
                                           (long long)IN_F * BB,
                                           pS, (long long)HB);
    bias_add<<<TT * HID_F * BB / 256, 256>>>(pS, bh);

    // 2) serial recurrence (fp32 SIMT, one launch per step)
    for (int t = 0; t < TT; ++t) {
        const float* src = (t == 0) ? h_prev : (pS + (long long)(t - 1) * HB);
        rnn_step<<<dim3(16, 8), 256>>>(Whh, src, pS + (long long)t * HB,
                                       t == 0 ? 0 : 1);
    }

    // 3) y_t = Why @ tanh(S[t]) + by  (tensor cores)
    wmma_gemm<true><<<dim3(8, TT), 256>>>(pW2h, pW2l, pS,
                                          (long long)HB,
                                          out, (long long)OUT_F * BB);
    bias_add<<<TT * OUT_F * BB / 256, 256>>>(out, by);

    // 4) h_final
    copy_final<<<512, 256>>>(out);
}

// round 11
// speedup vs baseline: 1.3308x; 1.1962x over previous
#include <cuda_runtime.h>
#include <cuda_bf16.h>
#include <mma.h>
#include <math.h>
#include <stdint.h>

using namespace nvcuda;

#define TT    256
#define IN_F  1024
#define HID_F 1024
#define OUT_F 1024
#define BB    128
#define HB    (HID_F * BB)
#define KDIM  1024
#define CH    32          // K chunk per mainloop iteration
#define KPA   40          // A smem k-pitch (conflict-free, 32B-aligned frags)
#define KPB   136         // B smem b-pitch (conflict-free, 32B-aligned frags)

// Scratch (__device__ globals; no allocations allowed)
__device__ float g_S[(size_t)TT * HB];             // pre-activation state (134 MB)
__device__ __nv_bfloat16 g_W1hi[(size_t)HID_F * IN_F];
__device__ __nv_bfloat16 g_W1lo[(size_t)HID_F * IN_F];
__device__ __nv_bfloat16 g_W2hi[(size_t)OUT_F * HID_F];
__device__ __nv_bfloat16 g_W2lo[(size_t)OUT_F * HID_F];

// ---------------------------------------------------------------------------
// Vectorized global reduction (PTX ISA 8.1+, sm_90+; arch-agnostic)
// ---------------------------------------------------------------------------
__device__ __forceinline__ void red_add_v4(float* p, float a, float b,
                                           float c, float d)
{
    asm volatile("red.global.add.v4.f32 [%0], {%1, %2, %3, %4};"
                 :: "l"(p), "f"(a), "f"(b), "f"(c), "f"(d) : "memory");
}

// ---------------------------------------------------------------------------
// Elementwise weight split: hi = bf16(w), lo = bf16(w - hi)
// ---------------------------------------------------------------------------
__global__ __launch_bounds__(256) void split_w(
    const float* __restrict__ W, __nv_bfloat16* __restrict__ hi,
    __nv_bfloat16* __restrict__ lo, int n)
{
    int i = blockIdx.x * 256 + threadIdx.x;
    if (i < n) {
        float v = W[i];
        __nv_bfloat16 h = __float2bfloat16_rn(v);
        hi[i] = h;
        lo[i] = __float2bfloat16_rn(v - __bfloat162float(h));
    }
}

// ---------------------------------------------------------------------------
// Tensor-core GEMM (wmma bf16, 3-pass split): one (m-tile, t) per CTA.
//   C[t][m0:m0+128][0:128] = Whi@Xhi + Whi@Xlo + Wlo@Xhi     (fp32 accum)
// ---------------------------------------------------------------------------
template <bool TANH>
__global__ __launch_bounds__(256) void wmma_gemm(
    const __nv_bfloat16* __restrict__ Whi, const __nv_bfloat16* __restrict__ Wlo,
    const float* __restrict__ Xb, long long xstride,
    float* __restrict__ Cb, long long cstride)
{
    __shared__ __align__(32) __nv_bfloat16 Ah[128][KPA];
    __shared__ __align__(32) __nv_bfloat16 Al[128][KPA];
    __shared__ __align__(32) __nv_bfloat16 Bh[CH][KPB];
    __shared__ __align__(32) __nv_bfloat16 Bl[CH][KPB];

    const int tid = threadIdx.x;
    const int wid = tid >> 5;
    const int m0  = blockIdx.x * 128;
    const int t   = blockIdx.y;
    const int wm  = wid >> 1;        // 0..3  -> rows wm*32..+32
    const int wn  = wid & 1;         // 0..1  -> cols wn*64..+64

    const __nv_bfloat16* WhP = Whi + (size_t)m0 * KDIM;
    const __nv_bfloat16* WlP = Wlo + (size_t)m0 * KDIM;
    const float*         X   = Xb + (long long)t * xstride;

    wmma::fragment<wmma::accumulator, 16, 16, 16, float> acc[2][4];
#pragma unroll
    for (int i = 0; i < 2; i++)
#pragma unroll
        for (int j = 0; j < 4; j++) wmma::fill_fragment(acc[i][j], 0.0f);

    uint4  aH[2], aL[2];
    float4 bx[4];

    auto load_regs = [&](int k0) {
#pragma unroll
        for (int q = 0; q < 2; q++) {
            const int v = tid + q * 256;
            const int row = v >> 2, kq = (v & 3) * 8;
            aH[q] = *(const uint4*)(WhP + (size_t)row * KDIM + k0 + kq);
            aL[q] = *(const uint4*)(WlP + (size_t)row * KDIM + k0 + kq);
        }
#pragma unroll
        for (int q = 0; q < 4; q++) {
            const int u = tid + q * 256;
            const int krow = u >> 5, bcol = (u & 31) * 4;
            bx[q] = *(const float4*)(X + (long long)(k0 + krow) * BB + bcol);
        }
    };

    load_regs(0);

    for (int c = 0; c < KDIM / CH; c++) {
#pragma unroll
        for (int q = 0; q < 2; q++) {
            const int v = tid + q * 256;
            const int row = v >> 2, kq = (v & 3) * 8;
            *(uint4*)&Ah[row][kq] = aH[q];
            *(uint4*)&Al[row][kq] = aL[q];
        }
#pragma unroll
        for (int q = 0; q < 4; q++) {
            const int u = tid + q * 256;
            const int krow = u >> 5, bcol = (u & 31) * 4;
            float4 f = bx[q];
            if (TANH) {
                f.x = tanhf(f.x); f.y = tanhf(f.y);
                f.z = tanhf(f.z); f.w = tanhf(f.w);
            }
            __nv_bfloat16 h0 = __float2bfloat16_rn(f.x);
            __nv_bfloat16 h1 = __float2bfloat16_rn(f.y);
            __nv_bfloat16 h2 = __float2bfloat16_rn(f.z);
            __nv_bfloat16 h3 = __float2bfloat16_rn(f.w);
            __nv_bfloat16 l0 = __float2bfloat16_rn(f.x - __bfloat162float(h0));
            __nv_bfloat16 l1 = __float2bfloat16_rn(f.y - __bfloat162float(h1));
            __nv_bfloat16 l2 = __float2bfloat16_rn(f.z - __bfloat162float(h2));
            __nv_bfloat16 l3 = __float2bfloat16_rn(f.w - __bfloat162float(h3));
            *(__nv_bfloat162*)&Bh[krow][bcol]     = __nv_bfloat162(h0, h1);
            *(__nv_bfloat162*)&Bh[krow][bcol + 2] = __nv_bfloat162(h2, h3);
            *(__nv_bfloat162*)&Bl[krow][bcol]     = __nv_bfloat162(l0, l1);
            *(__nv_bfloat162*)&Bl[krow][bcol + 2] = __nv_bfloat162(l2, l3);
        }
        __syncthreads();

        if (c + 1 < KDIM / CH) load_regs((c + 1) * CH);

#pragma unroll
        for (int kk = 0; kk < CH; kk += 16) {
            wmma::fragment<wmma::matrix_a, 16, 16, 16, __nv_bfloat16,
                           wmma::row_major> fah[2], fal[2];
            wmma::fragment<wmma::matrix_b, 16, 16, 16, __nv_bfloat16,
                           wmma::row_major> fbh[4], fbl[4];
#pragma unroll
            for (int i = 0; i < 2; i++) {
                wmma::load_matrix_sync(fah[i], &Ah[wm * 32 + i * 16][kk], KPA);
                wmma::load_matrix_sync(fal[i], &Al[wm * 32 + i * 16][kk], KPA);
            }
#pragma unroll
            for (int j = 0; j < 4; j++) {
                wmma::load_matrix_sync(fbh[j], &Bh[kk][wn * 64 + j * 16], KPB);
                wmma::load_matrix_sync(fbl[j], &Bl[kk][wn * 64 + j * 16], KPB);
            }
#pragma unroll
            for (int i = 0; i < 2; i++)
#pragma unroll
                for (int j = 0; j < 4; j++) {
                    wmma::mma_sync(acc[i][j], fah[i], fbh[j], acc[i][j]);
                    wmma::mma_sync(acc[i][j], fah[i], fbl[j], acc[i][j]);
                    wmma::mma_sync(acc[i][j], fal[i], fbh[j], acc[i][j]);
                }
        }
        __syncthreads();
    }

    float* C = Cb + (long long)t * cstride;
#pragma unroll
    for (int i = 0; i < 2; i++)
#pragma unroll
        for (int j = 0; j < 4; j++)
            wmma::store_matrix_sync(
                C + (long long)(m0 + wm * 32 + i * 16) * BB + wn * 64 + j * 16,
                acc[i][j], BB, wmma::mem_row_major);
}

// C[idx4] += bias[(idx>>7)&1023], float4-vectorized (stage-3 output only)
__global__ __launch_bounds__(256) void bias_add4(
    float* __restrict__ C, const float* __restrict__ bias)
{
    const long long e = ((long long)blockIdx.x * 256 + threadIdx.x) * 4;
    const float bv = bias[(e >> 7) & 1023];
    float4 v = *(float4*)(C + e);
    v.x += bv; v.y += bv; v.z += bv; v.w += bv;
    *(float4*)(C + e) = v;
}

// ---------------------------------------------------------------------------
// Recurrence step: dst += Whh[:,ks] @ tanh?(src[ks,:]) + bh/8
// (each of the 8 k-splits contributes bias/8 -> total bh added exactly once)
// grid (16 m-tiles, 8 k-splits), 256 threads; epilogue via red.add.v4.f32.
// ---------------------------------------------------------------------------
__global__ __launch_bounds__(256) void rnn_step(
    const float* __restrict__ Whh, const float* __restrict__ src,
    float* __restrict__ dst, const float* __restrict__ bias, int do_tanh)
{
    __shared__ float Ws[2][8][64];
    __shared__ float Xs[2][8][128];

    const int tid   = threadIdx.x;
    const int m0    = blockIdx.x * 64;
    const int kbase = blockIdx.y * 128;

    const float* Wp = Whh + (long long)kbase;
    const float* Hs = src + (long long)kbase * BB;

    const int tm = (tid >> 4) * 4;
    const int tn = (tid & 15) * 8;
    const int wrow = tid >> 2;
    const int wkq  = (tid & 3) * 2;
    const int xrow = tid >> 5;
    const int xcol = (tid & 31) * 4;

    float acc[4][8];
#pragma unroll
    for (int i = 0; i < 4; i++)
#pragma unroll
        for (int j = 0; j < 8; j++) acc[i][j] = 0.f;

    {
        float2 w = *(const float2*)(Wp + (long long)(m0 + wrow) * HID_F + wkq);
        float4 x = *(const float4*)(Hs + (long long)xrow * BB + xcol);
        if (do_tanh) {
            x.x = tanhf(x.x); x.y = tanhf(x.y);
            x.z = tanhf(x.z); x.w = tanhf(x.w);
        }
        Ws[0][wkq + 0][wrow] = w.x;
        Ws[0][wkq + 1][wrow] = w.y;
        *(float4*)&Xs[0][xrow][xcol] = x;
    }
    __syncthreads();

#pragma unroll 2
    for (int c = 0; c < 16; c++) {
        const int buf = c & 1;
        float2 wn2; float4 xn;
        if (c < 15) {
            const int kk0 = (c + 1) * 8;
            wn2 = *(const float2*)(Wp + (long long)(m0 + wrow) * HID_F + kk0 + wkq);
            xn  = *(const float4*)(Hs + (long long)(kk0 + xrow) * BB + xcol);
            if (do_tanh) {
                xn.x = tanhf(xn.x); xn.y = tanhf(xn.y);
                xn.z = tanhf(xn.z); xn.w = tanhf(xn.w);
            }
        }
#pragma unroll
        for (int kk = 0; kk < 8; kk++) {
            float a[4], bb[8];
            *(float4*)&a[0]  = *(const float4*)&Ws[buf][kk][tm];
            *(float4*)&bb[0] = *(const float4*)&Xs[buf][kk][tn];
            *(float4*)&bb[4] = *(const float4*)&Xs[buf][kk][tn + 4];
#pragma unroll
            for (int i = 0; i < 4; i++)
#pragma unroll
                for (int j = 0; j < 8; j++)
                    acc[i][j] += a[i] * bb[j];
        }
        if (c < 15) {
            Ws[buf ^ 1][wkq + 0][wrow] = wn2.x;
            Ws[buf ^ 1][wkq + 1][wrow] = wn2.y;
            *(float4*)&Xs[buf ^ 1][xrow][xcol] = xn;
        }
        __syncthreads();
    }

    // vectorized reduction epilogue (+ bh/8 folded in)
#pragma unroll
    for (int i = 0; i < 4; i++) {
        const float bv = bias[m0 + tm + i] * 0.125f;
        float* pr = dst + (long long)(m0 + tm + i) * BB + tn;
        red_add_v4(pr,     acc[i][0] + bv, acc[i][1] + bv,
                           acc[i][2] + bv, acc[i][3] + bv);
        red_add_v4(pr + 4, acc[i][4] + bv, acc[i][5] + bv,
                           acc[i][6] + bv, acc[i][7] + bv);
    }
}

// h_final = tanh(S[T-1])
__global__ __launch_bounds__(256) void copy_final(float* __restrict__ out)
{
    const int idx = blockIdx.x * 256 + threadIdx.x;
    out[(long long)TT * OUT_F * BB + idx] =
        tanhf(g_S[(long long)(TT - 1) * HB + idx]);
}

// ---------------------------------------------------------------------------
extern "C" void kernel_launch(void* const* d_in, const int* in_sizes, int n_in,
                              void* d_out, int out_size)
{
    (void)in_sizes; (void)n_in; (void)out_size;
    const float* inputs = (const float*)d_in[0];
    const float* h_prev = (const float*)d_in[1];
    const float* Wxh    = (const float*)d_in[2];
    const float* Whh    = (const float*)d_in[3];
    const float* Why    = (const float*)d_in[4];
    const float* bh     = (const float*)d_in[5];
    const float* by     = (const float*)d_in[6];
    float* out = (float*)d_out;

    float* pS = nullptr;
    __nv_bfloat16 *pW1h, *pW1l, *pW2h, *pW2l;
    cudaGetSymbolAddress((void**)&pS,  g_S);
    cudaGetSymbolAddress((void**)&pW1h, g_W1hi);
    cudaGetSymbolAddress((void**)&pW1l, g_W1lo);
    cudaGetSymbolAddress((void**)&pW2h, g_W2hi);
    cudaGetSymbolAddress((void**)&pW2l, g_W2lo);

    // weight splits
    split_w<<<4096, 256>>>(Wxh, pW1h, pW1l, HID_F * IN_F);
    split_w<<<4096, 256>>>(Why, pW2h, pW2l, OUT_F * HID_F);

    // 1) S[t] = Wxh @ x_t  (tensor cores; bh folded into step partials)
    wmma_gemm<false><<<dim3(8, TT), 256>>>(pW1h, pW1l, inputs,
                                           (long long)IN_F * BB,
                                           pS, (long long)HB);

    // 2) serial recurrence (fp32 SIMT, one launch per step, v4 reductions)
    for (int t = 0; t < TT; ++t) {
        const float* src = (t == 0) ? h_prev : (pS + (long long)(t - 1) * HB);
        rnn_step<<<dim3(16, 8), 256>>>(Whh, src, pS + (long long)t * HB,
                                       bh, t == 0 ? 0 : 1);
    }

    // 3) y_t = Why @ tanh(S[t])  (tensor cores), then + by
    wmma_gemm<true><<<dim3(8, TT), 256>>>(pW2h, pW2l, pS,
                                          (long long)HB,
                                          out, (long long)OUT_F * BB);
    bias_add4<<<TT * OUT_F * BB / 1024, 256>>>(out, by);

    // 4) h_final
    copy_final<<<512, 256>>>(out);
}

// round 12
// speedup vs baseline: 1.3388x; 1.0061x over previous
#include <cuda_runtime.h>
#include <cuda_bf16.h>
#include <mma.h>
#include <math.h>
#include <stdint.h>

using namespace nvcuda;

#define TT    256
#define IN_F  1024
#define HID_F 1024
#define OUT_F 1024
#define BB    128
#define HB    (HID_F * BB)
#define KDIM  1024
#define CH    32          // K chunk per mainloop iteration
#define KPA   40          // A smem k-pitch (conflict-free, 32B-aligned frags)
#define KPB   136         // B smem b-pitch (conflict-free, 32B-aligned frags)

// Scratch (__device__ globals; no allocations allowed)
__device__ float g_S[(size_t)TT * HB];             // pre-activation state (134 MB)
__device__ __nv_bfloat16 g_Xhi[(size_t)TT * HB];   // X hi split  (67 MB)
__device__ __nv_bfloat16 g_Xlo[(size_t)TT * HB];   // X lo split  (67 MB)
__device__ __nv_bfloat16 g_W1hi[(size_t)HID_F * IN_F];
__device__ __nv_bfloat16 g_W1lo[(size_t)HID_F * IN_F];
__device__ __nv_bfloat16 g_W2hi[(size_t)OUT_F * HID_F];
__device__ __nv_bfloat16 g_W2lo[(size_t)OUT_F * HID_F];

// ---------------------------------------------------------------------------
// Vectorized global reduction (PTX ISA 8.1+, sm_90+; arch-agnostic)
// ---------------------------------------------------------------------------
__device__ __forceinline__ void red_add_v4(float* p, float a, float b,
                                           float c, float d)
{
    asm volatile("red.global.add.v4.f32 [%0], {%1, %2, %3, %4};"
                 :: "l"(p), "f"(a), "f"(b), "f"(c), "f"(d) : "memory");
}

// ---------------------------------------------------------------------------
// Elementwise weight split: hi = bf16(w), lo = bf16(w - hi)
// ---------------------------------------------------------------------------
__global__ __launch_bounds__(256) void split_w(
    const float* __restrict__ W, __nv_bfloat16* __restrict__ hi,
    __nv_bfloat16* __restrict__ lo, int n)
{
    int i = blockIdx.x * 256 + threadIdx.x;
    if (i < n) {
        float v = W[i];
        __nv_bfloat16 h = __float2bfloat16_rn(v);
        hi[i] = h;
        lo[i] = __float2bfloat16_rn(v - __bfloat162float(h));
    }
}

// ---------------------------------------------------------------------------
// Elementwise X split (optional tanh), float4/thread. Layout unchanged
// [t][k][b] — exactly the B operand order the GEMM consumes.
// ---------------------------------------------------------------------------
template <bool TANH>
__global__ __launch_bounds__(256) void split_x(
    const float* __restrict__ src,
    __nv_bfloat16* __restrict__ hi, __nv_bfloat16* __restrict__ lo)
{
    const long long e = ((long long)blockIdx.x * 256 + threadIdx.x) * 4;
    float4 f = *(const float4*)(src + e);
    if (TANH) {
        f.x = tanhf(f.x); f.y = tanhf(f.y);
        f.z = tanhf(f.z); f.w = tanhf(f.w);
    }
    __nv_bfloat16 h0 = __float2bfloat16_rn(f.x);
    __nv_bfloat16 h1 = __float2bfloat16_rn(f.y);
    __nv_bfloat16 h2 = __float2bfloat16_rn(f.z);
    __nv_bfloat16 h3 = __float2bfloat16_rn(f.w);
    __nv_bfloat162 H0(h0, h1), H1(h2, h3);
    __nv_bfloat162 L0(__float2bfloat16_rn(f.x - __bfloat162float(h0)),
                      __float2bfloat16_rn(f.y - __bfloat162float(h1)));
    __nv_bfloat162 L1(__float2bfloat16_rn(f.z - __bfloat162float(h2)),
                      __float2bfloat16_rn(f.w - __bfloat162float(h3)));
    *(__nv_bfloat162*)(hi + e)     = H0;
    *(__nv_bfloat162*)(hi + e + 2) = H1;
    *(__nv_bfloat162*)(lo + e)     = L0;
    *(__nv_bfloat162*)(lo + e + 2) = L1;
}

// ---------------------------------------------------------------------------
// Tensor-core GEMM (wmma bf16, 3-pass split): one (m-tile, t) per CTA.
//   C[t][m0:m0+128][0:128] = Whi@Xhi + Whi@Xlo + Wlo@Xhi     (fp32 accum)
// All operands pre-split bf16; staging is a straight copy.
// 256 threads = 8 warps, 4x2 warp grid, each warp 32(m) x 64(n), 2x4 frags.
// ---------------------------------------------------------------------------
__global__ __launch_bounds__(256) void wmma_gemm(
    const __nv_bfloat16* __restrict__ Whi, const __nv_bfloat16* __restrict__ Wlo,
    const __nv_bfloat16* __restrict__ Xhi, const __nv_bfloat16* __restrict__ Xlo,
    float* __restrict__ Cb, long long cstride)
{
    __shared__ __align__(32) __nv_bfloat16 Ah[128][KPA];
    __shared__ __align__(32) __nv_bfloat16 Al[128][KPA];
    __shared__ __align__(32) __nv_bfloat16 Bh[CH][KPB];
    __shared__ __align__(32) __nv_bfloat16 Bl[CH][KPB];

    const int tid = threadIdx.x;
    const int wid = tid >> 5;
    const int m0  = blockIdx.x * 128;
    const int t   = blockIdx.y;
    const int wm  = wid >> 1;        // 0..3  -> rows wm*32..+32
    const int wn  = wid & 1;         // 0..1  -> cols wn*64..+64

    const __nv_bfloat16* WhP = Whi + (size_t)m0 * KDIM;
    const __nv_bfloat16* WlP = Wlo + (size_t)m0 * KDIM;
    const __nv_bfloat16* Xh  = Xhi + (size_t)t * HB;
    const __nv_bfloat16* Xl  = Xlo + (size_t)t * HB;

    wmma::fragment<wmma::accumulator, 16, 16, 16, float> acc[2][4];
#pragma unroll
    for (int i = 0; i < 2; i++)
#pragma unroll
        for (int j = 0; j < 4; j++) wmma::fill_fragment(acc[i][j], 0.0f);

    uint4 aH[2], aL[2], bH[2], bL[2];

    auto load_regs = [&](int k0) {
#pragma unroll
        for (int q = 0; q < 2; q++) {
            const int v = tid + q * 256;
            const int row = v >> 2, kq = (v & 3) * 8;
            aH[q] = *(const uint4*)(WhP + (size_t)row * KDIM + k0 + kq);
            aL[q] = *(const uint4*)(WlP + (size_t)row * KDIM + k0 + kq);
        }
#pragma unroll
        for (int q = 0; q < 2; q++) {
            const int u = tid + q * 256;          // 0..511
            const int krow = u >> 4;              // 0..31
            const int bcol = (u & 15) * 8;        // 0..120
            bH[q] = *(const uint4*)(Xh + (size_t)(k0 + krow) * BB + bcol);
            bL[q] = *(const uint4*)(Xl + (size_t)(k0 + krow) * BB + bcol);
        }
    };

    load_regs(0);

    for (int c = 0; c < KDIM / CH; c++) {
#pragma unroll
        for (int q = 0; q < 2; q++) {
            const int v = tid + q * 256;
            const int row = v >> 2, kq = (v & 3) * 8;
            *(uint4*)&Ah[row][kq] = aH[q];
            *(uint4*)&Al[row][kq] = aL[q];
        }
#pragma unroll
        for (int q = 0; q < 2; q++) {
            const int u = tid + q * 256;
            const int krow = u >> 4, bcol = (u & 15) * 8;
            *(uint4*)&Bh[krow][bcol] = bH[q];
            *(uint4*)&Bl[krow][bcol] = bL[q];
        }
        __syncthreads();

        if (c + 1 < KDIM / CH) load_regs((c + 1) * CH);

#pragma unroll
        for (int kk = 0; kk < CH; kk += 16) {
            wmma::fragment<wmma::matrix_a, 16, 16, 16, __nv_bfloat16,
                           wmma::row_major> fah[2], fal[2];
            wmma::fragment<wmma::matrix_b, 16, 16, 16, __nv_bfloat16,
                           wmma::row_major> fbh[4], fbl[4];
#pragma unroll
            for (int i = 0; i < 2; i++) {
                wmma::load_matrix_sync(fah[i], &Ah[wm * 32 + i * 16][kk], KPA);
                wmma::load_matrix_sync(fal[i], &Al[wm * 32 + i * 16][kk], KPA);
            }
#pragma unroll
            for (int j = 0; j < 4; j++) {
                wmma::load_matrix_sync(fbh[j], &Bh[kk][wn * 64 + j * 16], KPB);
                wmma::load_matrix_sync(fbl[j], &Bl[kk][wn * 64 + j * 16], KPB);
            }
#pragma unroll
            for (int i = 0; i < 2; i++)
#pragma unroll
                for (int j = 0; j < 4; j++) {
                    wmma::mma_sync(acc[i][j], fah[i], fbh[j], acc[i][j]);
                    wmma::mma_sync(acc[i][j], fah[i], fbl[j], acc[i][j]);
                    wmma::mma_sync(acc[i][j], fal[i], fbh[j], acc[i][j]);
                }
        }
        __syncthreads();
    }

    float* C = Cb + (long long)t * cstride;
#pragma unroll
    for (int i = 0; i < 2; i++)
#pragma unroll
        for (int j = 0; j < 4; j++)
            wmma::store_matrix_sync(
                C + (long long)(m0 + wm * 32 + i * 16) * BB + wn * 64 + j * 16,
                acc[i][j], BB, wmma::mem_row_major);
}

// C[idx4] += bias[(idx>>7)&1023], float4-vectorized (stage-3 output only)
__global__ __launch_bounds__(256) void bias_add4(
    float* __restrict__ C, const float* __restrict__ bias)
{
    const long long e = ((long long)blockIdx.x * 256 + threadIdx.x) * 4;
    const float bv = bias[(e >> 7) & 1023];
    float4 v = *(float4*)(C + e);
    v.x += bv; v.y += bv; v.z += bv; v.w += bv;
    *(float4*)(C + e) = v;
}

// ---------------------------------------------------------------------------
// Recurrence step: dst += Whh[:,ks] @ tanh?(src[ks,:]) + bh/8
// grid (16 m-tiles, 8 k-splits), 256 threads; epilogue via red.add.v4.f32.
// ---------------------------------------------------------------------------
__global__ __launch_bounds__(256) void rnn_step(
    const float* __restrict__ Whh, const float* __restrict__ src,
    float* __restrict__ dst, const float* __restrict__ bias, int do_tanh)
{
    __shared__ float Ws[2][8][64];
    __shared__ float Xs[2][8][128];

    const int tid   = threadIdx.x;
    const int m0    = blockIdx.x * 64;
    const int kbase = blockIdx.y * 128;

    const float* Wp = Whh + (long long)kbase;
    const float* Hs = src + (long long)kbase * BB;

    const int tm = (tid >> 4) * 4;
    const int tn = (tid & 15) * 8;
    const int wrow = tid >> 2;
    const int wkq  = (tid & 3) * 2;
    const int xrow = tid >> 5;
    const int xcol = (tid & 31) * 4;

    float acc[4][8];
#pragma unroll
    for (int i = 0; i < 4; i++)
#pragma unroll
        for (int j = 0; j < 8; j++) acc[i][j] = 0.f;

    {
        float2 w = *(const float2*)(Wp + (long long)(m0 + wrow) * HID_F + wkq);
        float4 x = *(const float4*)(Hs + (long long)xrow * BB + xcol);
        if (do_tanh) {
            x.x = tanhf(x.x); x.y = tanhf(x.y);
            x.z = tanhf(x.z); x.w = tanhf(x.w);
        }
        Ws[0][wkq + 0][wrow] = w.x;
        Ws[0][wkq + 1][wrow] = w.y;
        *(float4*)&Xs[0][xrow][xcol] = x;
    }
    __syncthreads();

#pragma unroll 2
    for (int c = 0; c < 16; c++) {
        const int buf = c & 1;
        float2 wn2; float4 xn;
        if (c < 15) {
            const int kk0 = (c + 1) * 8;
            wn2 = *(const float2*)(Wp + (long long)(m0 + wrow) * HID_F + kk0 + wkq);
            xn  = *(const float4*)(Hs + (long long)(kk0 + xrow) * BB + xcol);
            if (do_tanh) {
                xn.x = tanhf(xn.x); xn.y = tanhf(xn.y);
                xn.z = tanhf(xn.z); xn.w = tanhf(xn.w);
            }
        }
#pragma unroll
        for (int kk = 0; kk < 8; kk++) {
            float a[4], bb[8];
            *(float4*)&a[0]  = *(const float4*)&Ws[buf][kk][tm];
            *(float4*)&bb[0] = *(const float4*)&Xs[buf][kk][tn];
            *(float4*)&bb[4] = *(const float4*)&Xs[buf][kk][tn + 4];
#pragma unroll
            for (int i = 0; i < 4; i++)
#pragma unroll
                for (int j = 0; j < 8; j++)
                    acc[i][j] += a[i] * bb[j];
        }
        if (c < 15) {
            Ws[buf ^ 1][wkq + 0][wrow] = wn2.x;
            Ws[buf ^ 1][wkq + 1][wrow] = wn2.y;
            *(float4*)&Xs[buf ^ 1][xrow][xcol] = xn;
        }
        __syncthreads();
    }

#pragma unroll
    for (int i = 0; i < 4; i++) {
        const float bv = bias[m0 + tm + i] * 0.125f;
        float* pr = dst + (long long)(m0 + tm + i) * BB + tn;
        red_add_v4(pr,     acc[i][0] + bv, acc[i][1] + bv,
                           acc[i][2] + bv, acc[i][3] + bv);
        red_add_v4(pr + 4, acc[i][4] + bv, acc[i][5] + bv,
                           acc[i][6] + bv, acc[i][7] + bv);
    }
}

// h_final = tanh(S[T-1])
__global__ __launch_bounds__(256) void copy_final(float* __restrict__ out)
{
    const int idx = blockIdx.x * 256 + threadIdx.x;
    out[(long long)TT * OUT_F * BB + idx] =
        tanhf(g_S[(long long)(TT - 1) * HB + idx]);
}

// ---------------------------------------------------------------------------
extern "C" void kernel_launch(void* const* d_in, const int* in_sizes, int n_in,
                              void* d_out, int out_size)
{
    (void)in_sizes; (void)n_in; (void)out_size;
    const float* inputs = (const float*)d_in[0];
    const float* h_prev = (const float*)d_in[1];
    const float* Wxh    = (const float*)d_in[2];
    const float* Whh    = (const float*)d_in[3];
    const float* Why    = (const float*)d_in[4];
    const float* bh     = (const float*)d_in[5];
    const float* by     = (const float*)d_in[6];
    float* out = (float*)d_out;

    float* pS = nullptr;
    __nv_bfloat16 *pXh, *pXl, *pW1h, *pW1l, *pW2h, *pW2l;
    cudaGetSymbolAddress((void**)&pS,  g_S);
    cudaGetSymbolAddress((void**)&pXh, g_Xhi);
    cudaGetSymbolAddress((void**)&pXl, g_Xlo);
    cudaGetSymbolAddress((void**)&pW1h, g_W1hi);
    cudaGetSymbolAddress((void**)&pW1l, g_W1lo);
    cudaGetSymbolAddress((void**)&pW2h, g_W2hi);
    cudaGetSymbolAddress((void**)&pW2l, g_W2lo);

    // weight splits
    split_w<<<4096, 256>>>(Wxh, pW1h, pW1l, HID_F * IN_F);
    split_w<<<4096, 256>>>(Why, pW2h, pW2l, OUT_F * HID_F);

    // 1) split inputs once, then S[t] = Wxh @ x_t  (tensor cores)
    split_x<false><<<TT * HB / 1024, 256>>>(inputs, pXh, pXl);
    wmma_gemm<<<dim3(8, TT), 256>>>(pW1h, pW1l, pXh, pXl, pS, (long long)HB);

    // 2) serial recurrence (fp32 SIMT, one launch per step, v4 reductions)
    for (int t = 0; t < TT; ++t) {
        const float* src = (t == 0) ? h_prev : (pS + (long long)(t - 1) * HB);
        rnn_step<<<dim3(16, 8), 256>>>(Whh, src, pS + (long long)t * HB,
                                       bh, t == 0 ? 0 : 1);
    }

    // 3) split tanh(S) once, then y_t = Why @ h_t  (tensor cores), + by
    split_x<true><<<TT * HB / 1024, 256>>>(pS, pXh, pXl);
    wmma_gemm<<<dim3(8, TT), 256>>>(pW2h, pW2l, pXh, pXl, out,
                                    (long long)OUT_F * BB);
    bias_add4<<<TT * OUT_F * BB / 1024, 256>>>(out, by);

    // 4) h_final
    copy_final<<<512, 256>>>(out);
}

// round 13
// speedup vs baseline: 1.9717x; 1.4727x over previous
#include <cuda_runtime.h>
#include <cuda_bf16.h>
#include <mma.h>
#include <math.h>
#include <stdint.h>

using namespace nvcuda;

#define TT    256
#define IN_F  1024
#define HID_F 1024
#define OUT_F 1024
#define BB    128
#define HB    (HID_F * BB)
#define KDIM  1024
#define CH    32          // K chunk (outer GEMMs)
#define KPA   40          // A smem k-pitch (outer GEMMs)
#define KPB   136         // B smem pitch
#define SCH   32          // K chunk (step kernel)

// Scratch (__device__ globals; no allocations allowed)
__device__ float g_S[(size_t)TT * HB];             // pre-activation state (134 MB)
__device__ __nv_bfloat16 g_Xhi[(size_t)TT * HB];   // X hi split  (67 MB)
__device__ __nv_bfloat16 g_Xlo[(size_t)TT * HB];   // X lo split  (67 MB)
__device__ __nv_bfloat16 g_W1hi[(size_t)HID_F * IN_F];
__device__ __nv_bfloat16 g_W1lo[(size_t)HID_F * IN_F];
__device__ __nv_bfloat16 g_W2hi[(size_t)OUT_F * HID_F];
__device__ __nv_bfloat16 g_W2lo[(size_t)OUT_F * HID_F];
__device__ __nv_bfloat16 g_WHhi[(size_t)HID_F * HID_F];
__device__ __nv_bfloat16 g_WHlo[(size_t)HID_F * HID_F];

// ---------------------------------------------------------------------------
__device__ __forceinline__ void red_add_v4(float* p, float a, float b,
                                           float c, float d)
{
    asm volatile("red.global.add.v4.f32 [%0], {%1, %2, %3, %4};"
                 :: "l"(p), "f"(a), "f"(b), "f"(c), "f"(d) : "memory");
}

// ---------------------------------------------------------------------------
// Elementwise weight split: hi = bf16(w), lo = bf16(w - hi)
// ---------------------------------------------------------------------------
__global__ __launch_bounds__(256) void split_w(
    const float* __restrict__ W, __nv_bfloat16* __restrict__ hi,
    __nv_bfloat16* __restrict__ lo, int n)
{
    int i = blockIdx.x * 256 + threadIdx.x;
    if (i < n) {
        float v = W[i];
        __nv_bfloat16 h = __float2bfloat16_rn(v);
        hi[i] = h;
        lo[i] = __float2bfloat16_rn(v - __bfloat162float(h));
    }
}

// ---------------------------------------------------------------------------
// Elementwise X split (optional tanh), float4/thread.
// ---------------------------------------------------------------------------
template <bool TANH>
__global__ __launch_bounds__(256) void split_x(
    const float* __restrict__ src,
    __nv_bfloat16* __restrict__ hi, __nv_bfloat16* __restrict__ lo)
{
    const long long e = ((long long)blockIdx.x * 256 + threadIdx.x) * 4;
    float4 f = *(const float4*)(src + e);
    if (TANH) {
        f.x = tanhf(f.x); f.y = tanhf(f.y);
        f.z = tanhf(f.z); f.w = tanhf(f.w);
    }
    __nv_bfloat16 h0 = __float2bfloat16_rn(f.x);
    __nv_bfloat16 h1 = __float2bfloat16_rn(f.y);
    __nv_bfloat16 h2 = __float2bfloat16_rn(f.z);
    __nv_bfloat16 h3 = __float2bfloat16_rn(f.w);
    __nv_bfloat162 H0(h0, h1), H1(h2, h3);
    __nv_bfloat162 L0(__float2bfloat16_rn(f.x - __bfloat162float(h0)),
                      __float2bfloat16_rn(f.y - __bfloat162float(h1)));
    __nv_bfloat162 L1(__float2bfloat16_rn(f.z - __bfloat162float(h2)),
                      __float2bfloat16_rn(f.w - __bfloat162float(h3)));
    *(__nv_bfloat162*)(hi + e)     = H0;
    *(__nv_bfloat162*)(hi + e + 2) = H1;
    *(__nv_bfloat162*)(lo + e)     = L0;
    *(__nv_bfloat162*)(lo + e + 2) = L1;
}

// ---------------------------------------------------------------------------
// Outer tensor-core GEMM (wmma bf16, 3-pass split) — unchanged from R12.
// ---------------------------------------------------------------------------
__global__ __launch_bounds__(256) void wmma_gemm(
    const __nv_bfloat16* __restrict__ Whi, const __nv_bfloat16* __restrict__ Wlo,
    const __nv_bfloat16* __restrict__ Xhi, const __nv_bfloat16* __restrict__ Xlo,
    float* __restrict__ Cb, long long cstride)
{
    __shared__ __align__(32) __nv_bfloat16 Ah[128][KPA];
    __shared__ __align__(32) __nv_bfloat16 Al[128][KPA];
    __shared__ __align__(32) __nv_bfloat16 Bh[CH][KPB];
    __shared__ __align__(32) __nv_bfloat16 Bl[CH][KPB];

    const int tid = threadIdx.x;
    const int wid = tid >> 5;
    const int m0  = blockIdx.x * 128;
    const int t   = blockIdx.y;
    const int wm  = wid >> 1;
    const int wn  = wid & 1;

    const __nv_bfloat16* WhP = Whi + (size_t)m0 * KDIM;
    const __nv_bfloat16* WlP = Wlo + (size_t)m0 * KDIM;
    const __nv_bfloat16* Xh  = Xhi + (size_t)t * HB;
    const __nv_bfloat16* Xl  = Xlo + (size_t)t * HB;

    wmma::fragment<wmma::accumulator, 16, 16, 16, float> acc[2][4];
#pragma unroll
    for (int i = 0; i < 2; i++)
#pragma unroll
        for (int j = 0; j < 4; j++) wmma::fill_fragment(acc[i][j], 0.0f);

    uint4 aH[2], aL[2], bH[2], bL[2];

    auto load_regs = [&](int k0) {
#pragma unroll
        for (int q = 0; q < 2; q++) {
            const int v = tid + q * 256;
            const int row = v >> 2, kq = (v & 3) * 8;
            aH[q] = *(const uint4*)(WhP + (size_t)row * KDIM + k0 + kq);
            aL[q] = *(const uint4*)(WlP + (size_t)row * KDIM + k0 + kq);
        }
#pragma unroll
        for (int q = 0; q < 2; q++) {
            const int u = tid + q * 256;
            const int krow = u >> 4;
            const int bcol = (u & 15) * 8;
            bH[q] = *(const uint4*)(Xh + (size_t)(k0 + krow) * BB + bcol);
            bL[q] = *(const uint4*)(Xl + (size_t)(k0 + krow) * BB + bcol);
        }
    };

    load_regs(0);

    for (int c = 0; c < KDIM / CH; c++) {
#pragma unroll
        for (int q = 0; q < 2; q++) {
            const int v = tid + q * 256;
            const int row = v >> 2, kq = (v & 3) * 8;
            *(uint4*)&Ah[row][kq] = aH[q];
            *(uint4*)&Al[row][kq] = aL[q];
        }
#pragma unroll
        for (int q = 0; q < 2; q++) {
            const int u = tid + q * 256;
            const int krow = u >> 4, bcol = (u & 15) * 8;
            *(uint4*)&Bh[krow][bcol] = bH[q];
            *(uint4*)&Bl[krow][bcol] = bL[q];
        }
        __syncthreads();

        if (c + 1 < KDIM / CH) load_regs((c + 1) * CH);

#pragma unroll
        for (int kk = 0; kk < CH; kk += 16) {
            wmma::fragment<wmma::matrix_a, 16, 16, 16, __nv_bfloat16,
                           wmma::row_major> fah[2], fal[2];
            wmma::fragment<wmma::matrix_b, 16, 16, 16, __nv_bfloat16,
                           wmma::row_major> fbh[4], fbl[4];
#pragma unroll
            for (int i = 0; i < 2; i++) {
                wmma::load_matrix_sync(fah[i], &Ah[wm * 32 + i * 16][kk], KPA);
                wmma::load_matrix_sync(fal[i], &Al[wm * 32 + i * 16][kk], KPA);
            }
#pragma unroll
            for (int j = 0; j < 4; j++) {
                wmma::load_matrix_sync(fbh[j], &Bh[kk][wn * 64 + j * 16], KPB);
                wmma::load_matrix_sync(fbl[j], &Bl[kk][wn * 64 + j * 16], KPB);
            }
#pragma unroll
            for (int i = 0; i < 2; i++)
#pragma unroll
                for (int j = 0; j < 4; j++) {
                    wmma::mma_sync(acc[i][j], fah[i], fbh[j], acc[i][j]);
                    wmma::mma_sync(acc[i][j], fah[i], fbl[j], acc[i][j]);
                    wmma::mma_sync(acc[i][j], fal[i], fbh[j], acc[i][j]);
                }
        }
        __syncthreads();
    }

    float* C = Cb + (long long)t * cstride;
#pragma unroll
    for (int i = 0; i < 2; i++)
#pragma unroll
        for (int j = 0; j < 4; j++)
            wmma::store_matrix_sync(
                C + (long long)(m0 + wm * 32 + i * 16) * BB + wn * 64 + j * 16,
                acc[i][j], BB, wmma::mem_row_major);
}

// C[idx4] += bias[(idx>>7)&1023] (stage-3 output only)
__global__ __launch_bounds__(256) void bias_add4(
    float* __restrict__ C, const float* __restrict__ bias)
{
    const long long e = ((long long)blockIdx.x * 256 + threadIdx.x) * 4;
    const float bv = bias[(e >> 7) & 1023];
    float4 v = *(float4*)(C + e);
    v.x += bv; v.y += bv; v.z += bv; v.w += bv;
    *(float4*)(C + e) = v;
}

// ---------------------------------------------------------------------------
// Tensor-core recurrence step: dst += Whh[:,ks] @ tanh?(src[ks,:]) + bh/8
// grid (16 m-tiles, 8 k-splits), 256 threads. Per CTA: 64m x 128k x 128n,
// 3-pass bf16 split (Whh pre-split global; h tanh+split in-kernel to smem).
// K chunked by 32 with register prefetch; epilogue via smem + red.add.v4.
// ---------------------------------------------------------------------------
__global__ __launch_bounds__(256) void rnn_step_tc(
    const __nv_bfloat16* __restrict__ Whi, const __nv_bfloat16* __restrict__ Wlo,
    const float* __restrict__ src, float* __restrict__ dst,
    const float* __restrict__ bias, int do_tanh)
{
    // mainloop layout: Ah[64][40] @0 (5120B), Al @5120, Bh[32][136] @10240
    // (8704B), Bl @18944; total 27648. epilogue: float[64][132] @0 (33792B).
    __shared__ __align__(32) char sm[33792];
    __nv_bfloat16 (*Ah)[40]  = (__nv_bfloat16(*)[40])(sm);
    __nv_bfloat16 (*Al)[40]  = (__nv_bfloat16(*)[40])(sm + 5120);
    __nv_bfloat16 (*Bh)[136] = (__nv_bfloat16(*)[136])(sm + 10240);
    __nv_bfloat16 (*Bl)[136] = (__nv_bfloat16(*)[136])(sm + 18944);

    const int tid = threadIdx.x;
    const int wid = tid >> 5;
    const int m0  = blockIdx.x * 64;
    const int k0  = blockIdx.y * 128;
    const int wm  = wid >> 1;        // 0..3 -> rows wm*16
    const int wn  = wid & 1;         // 0..1 -> cols wn*64

    const __nv_bfloat16* WhP = Whi + (size_t)m0 * HID_F + k0;
    const __nv_bfloat16* WlP = Wlo + (size_t)m0 * HID_F + k0;
    const float*         Hs  = src + (size_t)k0 * BB;

    wmma::fragment<wmma::accumulator, 16, 16, 16, float> acc[4];
#pragma unroll
    for (int j = 0; j < 4; j++) wmma::fill_fragment(acc[j], 0.0f);

    uint4  aH, aL;
    float4 bx[4];
    const int arow = tid >> 2, akq = (tid & 3) * 8;   // A: 64x32 / 256 thr

    auto load_regs = [&](int c0) {
        aH = *(const uint4*)(WhP + (size_t)arow * HID_F + c0 + akq);
        aL = *(const uint4*)(WlP + (size_t)arow * HID_F + c0 + akq);
#pragma unroll
        for (int q = 0; q < 4; q++) {
            const int u = tid + q * 256;           // 0..1023
            const int krow = u >> 5;               // 0..31
            const int bcol = (u & 31) * 4;         // 0..124
            bx[q] = *(const float4*)(Hs + (size_t)(c0 + krow) * BB + bcol);
        }
    };

    load_regs(0);

    for (int c = 0; c < 128 / SCH; c++) {
        *(uint4*)&Ah[arow][akq] = aH;
        *(uint4*)&Al[arow][akq] = aL;
#pragma unroll
        for (int q = 0; q < 4; q++) {
            const int u = tid + q * 256;
            const int krow = u >> 5, bcol = (u & 31) * 4;
            float4 f = bx[q];
            if (do_tanh) {
                f.x = tanhf(f.x); f.y = tanhf(f.y);
                f.z = tanhf(f.z); f.w = tanhf(f.w);
            }
            __nv_bfloat16 h0 = __float2bfloat16_rn(f.x);
            __nv_bfloat16 h1 = __float2bfloat16_rn(f.y);
            __nv_bfloat16 h2 = __float2bfloat16_rn(f.z);
            __nv_bfloat16 h3 = __float2bfloat16_rn(f.w);
            *(__nv_bfloat162*)&Bh[krow][bcol]     = __nv_bfloat162(h0, h1);
            *(__nv_bfloat162*)&Bh[krow][bcol + 2] = __nv_bfloat162(h2, h3);
            *(__nv_bfloat162*)&Bl[krow][bcol] =
                __nv_bfloat162(__float2bfloat16_rn(f.x - __bfloat162float(h0)),
                               __float2bfloat16_rn(f.y - __bfloat162float(h1)));
            *(__nv_bfloat162*)&Bl[krow][bcol + 2] =
                __nv_bfloat162(__float2bfloat16_rn(f.z - __bfloat162float(h2)),
                               __float2bfloat16_rn(f.w - __bfloat162float(h3)));
        }
        __syncthreads();

        if (c + 1 < 128 / SCH) load_regs((c + 1) * SCH);

#pragma unroll
        for (int kk = 0; kk < SCH; kk += 16) {
            wmma::fragment<wmma::matrix_a, 16, 16, 16, __nv_bfloat16,
                           wmma::row_major> fah, fal;
            wmma::fragment<wmma::matrix_b, 16, 16, 16, __nv_bfloat16,
                           wmma::row_major> fbh[4], fbl[4];
            wmma::load_matrix_sync(fah, &Ah[wm * 16][kk], 40);
            wmma::load_matrix_sync(fal, &Al[wm * 16][kk], 40);
#pragma unroll
            for (int j = 0; j < 4; j++) {
                wmma::load_matrix_sync(fbh[j], &Bh[kk][wn * 64 + j * 16], 136);
                wmma::load_matrix_sync(fbl[j], &Bl[kk][wn * 64 + j * 16], 136);
            }
#pragma unroll
            for (int j = 0; j < 4; j++) {
                wmma::mma_sync(acc[j], fah, fbh[j], acc[j]);
                wmma::mma_sync(acc[j], fah, fbl[j], acc[j]);
                wmma::mma_sync(acc[j], fal, fbh[j], acc[j]);
            }
        }
        __syncthreads();
    }

    // epilogue: frags -> smem (fp32, pitch 132) -> red.add.v4 with bh/8
    float (*Ep)[132] = (float(*)[132])sm;
#pragma unroll
    for (int j = 0; j < 4; j++)
        wmma::store_matrix_sync(&Ep[wm * 16][wn * 64 + j * 16], acc[j], 132,
                                wmma::mem_row_major);
    __syncthreads();

#pragma unroll
    for (int it = 0; it < 8; it++) {
        const int idx = tid + it * 256;          // 0..2047
        const int row = idx >> 5;                // 0..63
        const int col = (idx & 31) * 4;          // 0..124
        float4 v = *(const float4*)&Ep[row][col];
        const float bv = bias[m0 + row] * 0.125f;
        red_add_v4(dst + (size_t)(m0 + row) * BB + col,
                   v.x + bv, v.y + bv, v.z + bv, v.w + bv);
    }
}

// h_final = tanh(S[T-1])
__global__ __launch_bounds__(256) void copy_final(float* __restrict__ out)
{
    const int idx = blockIdx.x * 256 + threadIdx.x;
    out[(long long)TT * OUT_F * BB + idx] =
        tanhf(g_S[(long long)(TT - 1) * HB + idx]);
}

// ---------------------------------------------------------------------------
extern "C" void kernel_launch(void* const* d_in, const int* in_sizes, int n_in,
                              void* d_out, int out_size)
{
    (void)in_sizes; (void)n_in; (void)out_size;
    const float* inputs = (const float*)d_in[0];
    const float* h_prev = (const float*)d_in[1];
    const float* Wxh    = (const float*)d_in[2];
    const float* Whh    = (const float*)d_in[3];
    const float* Why    = (const float*)d_in[4];
    const float* bh     = (const float*)d_in[5];
    const float* by     = (const float*)d_in[6];
    float* out = (float*)d_out;

    float* pS = nullptr;
    __nv_bfloat16 *pXh, *pXl, *pW1h, *pW1l, *pW2h, *pW2l, *pWHh, *pWHl;
    cudaGetSymbolAddress((void**)&pS,  g_S);
    cudaGetSymbolAddress((void**)&pXh, g_Xhi);
    cudaGetSymbolAddress((void**)&pXl, g_Xlo);
    cudaGetSymbolAddress((void**)&pW1h, g_W1hi);
    cudaGetSymbolAddress((void**)&pW1l, g_W1lo);
    cudaGetSymbolAddress((void**)&pW2h, g_W2hi);
    cudaGetSymbolAddress((void**)&pW2l, g_W2lo);
    cudaGetSymbolAddress((void**)&pWHh, g_WHhi);
    cudaGetSymbolAddress((void**)&pWHl, g_WHlo);

    // weight splits
    split_w<<<4096, 256>>>(Wxh, pW1h, pW1l, HID_F * IN_F);
    split_w<<<4096, 256>>>(Whh, pWHh, pWHl, HID_F * HID_F);
    split_w<<<4096, 256>>>(Why, pW2h, pW2l, OUT_F * HID_F);

    // 1) split inputs once, then S[t] = Wxh @ x_t  (tensor cores)
    split_x<false><<<TT * HB / 1024, 256>>>(inputs, pXh, pXl);
    wmma_gemm<<<dim3(8, TT), 256>>>(pW1h, pW1l, pXh, pXl, pS, (long long)HB);

    // 2) serial recurrence (tensor cores, one launch per step)
    for (int t = 0; t < TT; ++t) {
        const float* src = (t == 0) ? h_prev : (pS + (long long)(t - 1) * HB);
        rnn_step_tc<<<dim3(16, 8), 256>>>(pWHh, pWHl, src,
                                          pS + (long long)t * HB,
                                          bh, t == 0 ? 0 : 1);
    }

    // 3) split tanh(S) once, then y_t = Why @ h_t  (tensor cores), + by
    split_x<true><<<TT * HB / 1024, 256>>>(pS, pXh, pXl);
    wmma_gemm<<<dim3(8, TT), 256>>>(pW2h, pW2l, pXh, pXl, out,
                                    (long long)OUT_F * BB);
    bias_add4<<<TT * OUT_F * BB / 1024, 256>>>(out, by);

    // 4) h_final
    copy_final<<<512, 256>>>(out);
}

// round 14
// speedup vs baseline: 2.1603x; 1.0956x over previous
#include <cuda_runtime.h>
#include <cuda_bf16.h>
#include <mma.h>
#include <math.h>
#include <stdint.h>

using namespace nvcuda;

#define TT    256
#define IN_F  1024
#define HID_F 1024
#define OUT_F 1024
#define BB    128
#define HB    (HID_F * BB)
#define KDIM  1024
#define CH    32          // K chunk (outer GEMMs)
#define KPA   40          // A smem k-pitch (elements)
#define KPB   136         // B smem pitch (elements)
#define SCH   32          // K chunk (step kernel)

// dynamic smem for wmma_gemm: 2 stages x (Ah+Al+Bh+Bl)
#define A_BYTES   (128 * KPA * 2)            // 10240
#define B_BYTES   (CH * KPB * 2)             // 8704
#define STG_BYTES (2 * A_BYTES + 2 * B_BYTES) // 37888
#define GSMEM     (2 * STG_BYTES)            // 75776

// Scratch (__device__ globals; no allocations allowed)
__device__ float g_S[(size_t)TT * HB];             // pre-activation state
__device__ __nv_bfloat16 g_Xhi[(size_t)TT * HB];
__device__ __nv_bfloat16 g_Xlo[(size_t)TT * HB];
__device__ __nv_bfloat16 g_W1hi[(size_t)HID_F * IN_F];
__device__ __nv_bfloat16 g_W1lo[(size_t)HID_F * IN_F];
__device__ __nv_bfloat16 g_W2hi[(size_t)OUT_F * HID_F];
__device__ __nv_bfloat16 g_W2lo[(size_t)OUT_F * HID_F];
__device__ __nv_bfloat16 g_WHhi[(size_t)HID_F * HID_F];
__device__ __nv_bfloat16 g_WHlo[(size_t)HID_F * HID_F];

// ---------------------------------------------------------------------------
__device__ __forceinline__ void red_add_v4(float* p, float a, float b,
                                           float c, float d)
{
    asm volatile("red.global.add.v4.f32 [%0], {%1, %2, %3, %4};"
                 :: "l"(p), "f"(a), "f"(b), "f"(c), "f"(d) : "memory");
}
__device__ __forceinline__ void cp16(void* dst_smem, const void* src)
{
    uint32_t d = (uint32_t)__cvta_generic_to_shared(dst_smem);
    asm volatile("cp.async.ca.shared.global [%0], [%1], 16;"
                 :: "r"(d), "l"(src) : "memory");
}
__device__ __forceinline__ void cp_commit()
{
    asm volatile("cp.async.commit_group;" ::: "memory");
}
template <int N>
__device__ __forceinline__ void cp_wait()
{
    asm volatile("cp.async.wait_group %0;" :: "n"(N) : "memory");
}

// ---------------------------------------------------------------------------
// Elementwise weight split: hi = bf16(w), lo = bf16(w - hi)
// ---------------------------------------------------------------------------
__global__ __launch_bounds__(256) void split_w(
    const float* __restrict__ W, __nv_bfloat16* __restrict__ hi,
    __nv_bfloat16* __restrict__ lo, int n)
{
    int i = blockIdx.x * 256 + threadIdx.x;
    if (i < n) {
        float v = W[i];
        __nv_bfloat16 h = __float2bfloat16_rn(v);
        hi[i] = h;
        lo[i] = __float2bfloat16_rn(v - __bfloat162float(h));
    }
}

// ---------------------------------------------------------------------------
// Elementwise X split (optional tanh), float4/thread.
// ---------------------------------------------------------------------------
template <bool TANH>
__global__ __launch_bounds__(256) void split_x(
    const float* __restrict__ src,
    __nv_bfloat16* __restrict__ hi, __nv_bfloat16* __restrict__ lo)
{
    const long long e = ((long long)blockIdx.x * 256 + threadIdx.x) * 4;
    float4 f = *(const float4*)(src + e);
    if (TANH) {
        f.x = tanhf(f.x); f.y = tanhf(f.y);
        f.z = tanhf(f.z); f.w = tanhf(f.w);
    }
    __nv_bfloat16 h0 = __float2bfloat16_rn(f.x);
    __nv_bfloat16 h1 = __float2bfloat16_rn(f.y);
    __nv_bfloat16 h2 = __float2bfloat16_rn(f.z);
    __nv_bfloat16 h3 = __float2bfloat16_rn(f.w);
    __nv_bfloat162 H0(h0, h1), H1(h2, h3);
    __nv_bfloat162 L0(__float2bfloat16_rn(f.x - __bfloat162float(h0)),
                      __float2bfloat16_rn(f.y - __bfloat162float(h1)));
    __nv_bfloat162 L1(__float2bfloat16_rn(f.z - __bfloat162float(h2)),
                      __float2bfloat16_rn(f.w - __bfloat162float(h3)));
    *(__nv_bfloat162*)(hi + e)     = H0;
    *(__nv_bfloat162*)(hi + e + 2) = H1;
    *(__nv_bfloat162*)(lo + e)     = L0;
    *(__nv_bfloat162*)(lo + e + 2) = L1;
}

// ---------------------------------------------------------------------------
// Outer tensor-core GEMM (wmma bf16, 3-pass split) with cp.async 2-stage
// pipeline: chunk c+1 streams global->smem while chunk c does MMAs.
// ---------------------------------------------------------------------------
__global__ __launch_bounds__(256) void wmma_gemm(
    const __nv_bfloat16* __restrict__ Whi, const __nv_bfloat16* __restrict__ Wlo,
    const __nv_bfloat16* __restrict__ Xhi, const __nv_bfloat16* __restrict__ Xlo,
    float* __restrict__ Cb, long long cstride)
{
    extern __shared__ __align__(16) char sm[];

    const int tid = threadIdx.x;
    const int wid = tid >> 5;
    const int m0  = blockIdx.x * 128;
    const int t   = blockIdx.y;
    const int wm  = wid >> 1;
    const int wn  = wid & 1;

    const __nv_bfloat16* WhP = Whi + (size_t)m0 * KDIM;
    const __nv_bfloat16* WlP = Wlo + (size_t)m0 * KDIM;
    const __nv_bfloat16* Xh  = Xhi + (size_t)t * HB;
    const __nv_bfloat16* Xl  = Xlo + (size_t)t * HB;

    wmma::fragment<wmma::accumulator, 16, 16, 16, float> acc[2][4];
#pragma unroll
    for (int i = 0; i < 2; i++)
#pragma unroll
        for (int j = 0; j < 4; j++) wmma::fill_fragment(acc[i][j], 0.0f);

    // A map: 512 cp16 / array -> 2/thread: row = v>>2, kq = (v&3)*8 elems
    // B map: 512 cp16 / array -> 2/thread: krow = u>>4, bcol = (u&15)*8 elems
    auto load_chunk = [&](int k0, int s) {
        char* base = sm + s * STG_BYTES;
        char* Ahp = base;
        char* Alp = base + A_BYTES;
        char* Bhp = base + 2 * A_BYTES;
        char* Blp = base + 2 * A_BYTES + B_BYTES;
#pragma unroll
        for (int q = 0; q < 2; q++) {
            const int v = tid + q * 256;
            const int row = v >> 2, kq = (v & 3) * 8;
            cp16(Ahp + row * (KPA * 2) + kq * 2,
                 WhP + (size_t)row * KDIM + k0 + kq);
            cp16(Alp + row * (KPA * 2) + kq * 2,
                 WlP + (size_t)row * KDIM + k0 + kq);
        }
#pragma unroll
        for (int q = 0; q < 2; q++) {
            const int u = tid + q * 256;
            const int krow = u >> 4, bcol = (u & 15) * 8;
            cp16(Bhp + krow * (KPB * 2) + bcol * 2,
                 Xh + (size_t)(k0 + krow) * BB + bcol);
            cp16(Blp + krow * (KPB * 2) + bcol * 2,
                 Xl + (size_t)(k0 + krow) * BB + bcol);
        }
        cp_commit();
    };

    load_chunk(0, 0);

    for (int c = 0; c < KDIM / CH; c++) {
        const int s = c & 1;
        if (c + 1 < KDIM / CH) {
            load_chunk((c + 1) * CH, s ^ 1);
            cp_wait<1>();          // chunk c resident; c+1 in flight
        } else {
            cp_wait<0>();
        }
        __syncthreads();

        char* base = sm + s * STG_BYTES;
        __nv_bfloat16 (*Ah)[KPA] = (__nv_bfloat16(*)[KPA])(base);
        __nv_bfloat16 (*Al)[KPA] = (__nv_bfloat16(*)[KPA])(base + A_BYTES);
        __nv_bfloat16 (*Bh)[KPB] = (__nv_bfloat16(*)[KPB])(base + 2 * A_BYTES);
        __nv_bfloat16 (*Bl)[KPB] =
            (__nv_bfloat16(*)[KPB])(base + 2 * A_BYTES + B_BYTES);

#pragma unroll
        for (int kk = 0; kk < CH; kk += 16) {
            wmma::fragment<wmma::matrix_a, 16, 16, 16, __nv_bfloat16,
                           wmma::row_major> fah[2], fal[2];
            wmma::fragment<wmma::matrix_b, 16, 16, 16, __nv_bfloat16,
                           wmma::row_major> fbh[4], fbl[4];
#pragma unroll
            for (int i = 0; i < 2; i++) {
                wmma::load_matrix_sync(fah[i], &Ah[wm * 32 + i * 16][kk], KPA);
                wmma::load_matrix_sync(fal[i], &Al[wm * 32 + i * 16][kk], KPA);
            }
#pragma unroll
            for (int j = 0; j < 4; j++) {
                wmma::load_matrix_sync(fbh[j], &Bh[kk][wn * 64 + j * 16], KPB);
                wmma::load_matrix_sync(fbl[j], &Bl[kk][wn * 64 + j * 16], KPB);
            }
#pragma unroll
            for (int i = 0; i < 2; i++)
#pragma unroll
                for (int j = 0; j < 4; j++) {
                    wmma::mma_sync(acc[i][j], fah[i], fbh[j], acc[i][j]);
                    wmma::mma_sync(acc[i][j], fah[i], fbl[j], acc[i][j]);
                    wmma::mma_sync(acc[i][j], fal[i], fbh[j], acc[i][j]);
                }
        }
        __syncthreads();   // all warps done reading stage s before it refills
    }

    float* C = Cb + (long long)t * cstride;
#pragma unroll
    for (int i = 0; i < 2; i++)
#pragma unroll
        for (int j = 0; j < 4; j++)
            wmma::store_matrix_sync(
                C + (long long)(m0 + wm * 32 + i * 16) * BB + wn * 64 + j * 16,
                acc[i][j], BB, wmma::mem_row_major);
}

// C[idx4] += bias[(idx>>7)&1023] (stage-3 output only)
__global__ __launch_bounds__(256) void bias_add4(
    float* __restrict__ C, const float* __restrict__ bias)
{
    const long long e = ((long long)blockIdx.x * 256 + threadIdx.x) * 4;
    const float bv = bias[(e >> 7) & 1023];
    float4 v = *(float4*)(C + e);
    v.x += bv; v.y += bv; v.z += bv; v.w += bv;
    *(float4*)(C + e) = v;
}

// ---------------------------------------------------------------------------
// Tensor-core recurrence step — UNCHANGED from R13 (proven, ~8.7 us).
// ---------------------------------------------------------------------------
__global__ __launch_bounds__(256) void rnn_step_tc(
    const __nv_bfloat16* __restrict__ Whi, const __nv_bfloat16* __restrict__ Wlo,
    const float* __restrict__ src, float* __restrict__ dst,
    const float* __restrict__ bias, int do_tanh)
{
    __shared__ __align__(32) char sm[33792];
    __nv_bfloat16 (*Ah)[40]  = (__nv_bfloat16(*)[40])(sm);
    __nv_bfloat16 (*Al)[40]  = (__nv_bfloat16(*)[40])(sm + 5120);
    __nv_bfloat16 (*Bh)[136] = (__nv_bfloat16(*)[136])(sm + 10240);
    __nv_bfloat16 (*Bl)[136] = (__nv_bfloat16(*)[136])(sm + 18944);

    const int tid = threadIdx.x;
    const int wid = tid >> 5;
    const int m0  = blockIdx.x * 64;
    const int k0  = blockIdx.y * 128;
    const int wm  = wid >> 1;
    const int wn  = wid & 1;

    const __nv_bfloat16* WhP = Whi + (size_t)m0 * HID_F + k0;
    const __nv_bfloat16* WlP = Wlo + (size_t)m0 * HID_F + k0;
    const float*         Hs  = src + (size_t)k0 * BB;

    wmma::fragment<wmma::accumulator, 16, 16, 16, float> acc[4];
#pragma unroll
    for (int j = 0; j < 4; j++) wmma::fill_fragment(acc[j], 0.0f);

    uint4  aH, aL;
    float4 bx[4];
    const int arow = tid >> 2, akq = (tid & 3) * 8;

    auto load_regs = [&](int c0) {
        aH = *(const uint4*)(WhP + (size_t)arow * HID_F + c0 + akq);
        aL = *(const uint4*)(WlP + (size_t)arow * HID_F + c0 + akq);
#pragma unroll
        for (int q = 0; q < 4; q++) {
            const int u = tid + q * 256;
            const int krow = u >> 5;
            const int bcol = (u & 31) * 4;
            bx[q] = *(const float4*)(Hs + (size_t)(c0 + krow) * BB + bcol);
        }
    };

    load_regs(0);

    for (int c = 0; c < 128 / SCH; c++) {
        *(uint4*)&Ah[arow][akq] = aH;
        *(uint4*)&Al[arow][akq] = aL;
#pragma unroll
        for (int q = 0; q < 4; q++) {
            const int u = tid + q * 256;
            const int krow = u >> 5, bcol = (u & 31) * 4;
            float4 f = bx[q];
            if (do_tanh) {
                f.x = tanhf(f.x); f.y = tanhf(f.y);
                f.z = tanhf(f.z); f.w = tanhf(f.w);
            }
            __nv_bfloat16 h0 = __float2bfloat16_rn(f.x);
            __nv_bfloat16 h1 = __float2bfloat16_rn(f.y);
            __nv_bfloat16 h2 = __float2bfloat16_rn(f.z);
            __nv_bfloat16 h3 = __float2bfloat16_rn(f.w);
            *(__nv_bfloat162*)&Bh[krow][bcol]     = __nv_bfloat162(h0, h1);
            *(__nv_bfloat162*)&Bh[krow][bcol + 2] = __nv_bfloat162(h2, h3);
            *(__nv_bfloat162*)&Bl[krow][bcol] =
                __nv_bfloat162(__float2bfloat16_rn(f.x - __bfloat162float(h0)),
                               __float2bfloat16_rn(f.y - __bfloat162float(h1)));
            *(__nv_bfloat162*)&Bl[krow][bcol + 2] =
                __nv_bfloat162(__float2bfloat16_rn(f.z - __bfloat162float(h2)),
                               __float2bfloat16_rn(f.w - __bfloat162float(h3)));
        }
        __syncthreads();

        if (c + 1 < 128 / SCH) load_regs((c + 1) * SCH);

#pragma unroll
        for (int kk = 0; kk < SCH; kk += 16) {
            wmma::fragment<wmma::matrix_a, 16, 16, 16, __nv_bfloat16,
                           wmma::row_major> fah, fal;
            wmma::fragment<wmma::matrix_b, 16, 16, 16, __nv_bfloat16,
                           wmma::row_major> fbh[4], fbl[4];
            wmma::load_matrix_sync(fah, &Ah[wm * 16][kk], 40);
            wmma::load_matrix_sync(fal, &Al[wm * 16][kk], 40);
#pragma unroll
            for (int j = 0; j < 4; j++) {
                wmma::load_matrix_sync(fbh[j], &Bh[kk][wn * 64 + j * 16], 136);
                wmma::load_matrix_sync(fbl[j], &Bl[kk][wn * 64 + j * 16], 136);
            }
#pragma unroll
            for (int j = 0; j < 4; j++) {
                wmma::mma_sync(acc[j], fah, fbh[j], acc[j]);
                wmma::mma_sync(acc[j], fah, fbl[j], acc[j]);
                wmma::mma_sync(acc[j], fal, fbh[j], acc[j]);
            }
        }
        __syncthreads();
    }

    float (*Ep)[132] = (float(*)[132])sm;
#pragma unroll
    for (int j = 0; j < 4; j++)
        wmma::store_matrix_sync(&Ep[wm * 16][wn * 64 + j * 16], acc[j], 132,
                                wmma::mem_row_major);
    __syncthreads();

#pragma unroll
    for (int it = 0; it < 8; it++) {
        const int idx = tid + it * 256;
        const int row = idx >> 5;
        const int col = (idx & 31) * 4;
        float4 v = *(const float4*)&Ep[row][col];
        const float bv = bias[m0 + row] * 0.125f;
        red_add_v4(dst + (size_t)(m0 + row) * BB + col,
                   v.x + bv, v.y + bv, v.z + bv, v.w + bv);
    }
}

// h_final = tanh(S[T-1])
__global__ __launch_bounds__(256) void copy_final(float* __restrict__ out)
{
    const int idx = blockIdx.x * 256 + threadIdx.x;
    out[(long long)TT * OUT_F * BB + idx] =
        tanhf(g_S[(long long)(TT - 1) * HB + idx]);
}

// ---------------------------------------------------------------------------
extern "C" void kernel_launch(void* const* d_in, const int* in_sizes, int n_in,
                              void* d_out, int out_size)
{
    (void)in_sizes; (void)n_in; (void)out_size;
    const float* inputs = (const float*)d_in[0];
    const float* h_prev = (const float*)d_in[1];
    const float* Wxh    = (const float*)d_in[2];
    const float* Whh    = (const float*)d_in[3];
    const float* Why    = (const float*)d_in[4];
    const float* bh     = (const float*)d_in[5];
    const float* by     = (const float*)d_in[6];
    float* out = (float*)d_out;

    float* pS = nullptr;
    __nv_bfloat16 *pXh, *pXl, *pW1h, *pW1l, *pW2h, *pW2l, *pWHh, *pWHl;
    cudaGetSymbolAddress((void**)&pS,  g_S);
    cudaGetSymbolAddress((void**)&pXh, g_Xhi);
    cudaGetSymbolAddress((void**)&pXl, g_Xlo);
    cudaGetSymbolAddress((void**)&pW1h, g_W1hi);
    cudaGetSymbolAddress((void**)&pW1l, g_W1lo);
    cudaGetSymbolAddress((void**)&pW2h, g_W2hi);
    cudaGetSymbolAddress((void**)&pW2l, g_W2lo);
    cudaGetSymbolAddress((void**)&pWHh, g_WHhi);
    cudaGetSymbolAddress((void**)&pWHl, g_WHlo);

    cudaFuncSetAttribute(wmma_gemm,
                         cudaFuncAttributeMaxDynamicSharedMemorySize, GSMEM);

    // weight splits
    split_w<<<4096, 256>>>(Wxh, pW1h, pW1l, HID_F * IN_F);
    split_w<<<4096, 256>>>(Whh, pWHh, pWHl, HID_F * HID_F);
    split_w<<<4096, 256>>>(Why, pW2h, pW2l, OUT_F * HID_F);

    // 1) split inputs once, then S[t] = Wxh @ x_t  (tensor cores, pipelined)
    split_x<false><<<TT * HB / 1024, 256>>>(inputs, pXh, pXl);
    wmma_gemm<<<dim3(8, TT), 256, GSMEM>>>(pW1h, pW1l, pXh, pXl, pS,
                                           (long long)HB);

    // 2) serial recurrence (tensor cores, one launch per step)
    for (int t = 0; t < TT; ++t) {
        const float* src = (t == 0) ? h_prev : (pS + (long long)(t - 1) * HB);
        rnn_step_tc<<<dim3(16, 8), 256>>>(pWHh, pWHl, src,
                                          pS + (long long)t * HB,
                                          bh, t == 0 ? 0 : 1);
    }

    // 3) split tanh(S) once, then y_t = Why @ h_t  (tensor cores), + by
    split_x<true><<<TT * HB / 1024, 256>>>(pS, pXh, pXl);
    wmma_gemm<<<dim3(8, TT), 256, GSMEM>>>(pW2h, pW2l, pXh, pXl, out,
                                           (long long)OUT_F * BB);
    bias_add4<<<TT * OUT_F * BB / 1024, 256>>>(out, by);

    // 4) h_final
    copy_final<<<512, 256>>>(out);
}